// round 9
// baseline (speedup 1.0000x reference)
#include <cuda_runtime.h>

#define D     256
#define NB    30
#define NP    32      // padded rows
#define RT    8       // rows per thread (4 row-groups)
#define EG    240
#define BG    2048
#define GAUX  32      // graphs per aux CTA

// fused fp32x2 FMA: acc.lo += a.lo*b.lo; acc.hi += a.hi*b.hi
#define FMA2(d, a, b) \
    asm("fma.rn.f32x2 %0, %1, %2, %0;" : "+l"(d) : "l"(a), "l"(b))

// Precomputed folded input-MLP matrices
__device__ float g_Mgeo[5 * D];
__device__ float g_Msem[11 * D];
__device__ float g_bias0[D];
// pooled per-graph features [g][4*256]
__device__ float g_gbuf[BG * 4 * D];
// K-pair + col-pair packed message weights:
//   g_Wp2[l][kp2*128 + cp] = { (W[k0][2cp],W[k0+1][2cp]), (W[k0][2cp+1],W[k0+1][2cp+1]) }
//   where kp2 in [0,256) spans both halves (h-part then xa-part), k0 = 2*kp2.
__device__ ulonglong2 g_Wp2[3][256 * 128];

// ---------------------------------------------------------------------------
__global__ void pre_kernel(const float* __restrict__ Wgeo,
                           const float* __restrict__ bgeo,
                           const float* __restrict__ emb,
                           const float* __restrict__ Wlot,
                           const float* __restrict__ blot)
{
    int c = threadIdx.x;
    int r = blockIdx.x;
    float a0 = 0.f, a1 = 0.f, a2 = 0.f, a3 = 0.f;
    if (r < 5) {
        for (int j = 0; j < D; j += 4) {
            a0 = fmaf(Wgeo[r * D + j + 0], Wlot[(j + 0) * D + c], a0);
            a1 = fmaf(Wgeo[r * D + j + 1], Wlot[(j + 1) * D + c], a1);
            a2 = fmaf(Wgeo[r * D + j + 2], Wlot[(j + 2) * D + c], a2);
            a3 = fmaf(Wgeo[r * D + j + 3], Wlot[(j + 3) * D + c], a3);
        }
        g_Mgeo[r * D + c] = (a0 + a1) + (a2 + a3);
    } else if (r < 16) {
        int s = r - 5;
        for (int j = 0; j < D; j += 4) {
            a0 = fmaf(emb[s * D + j + 0], Wlot[(D + j + 0) * D + c], a0);
            a1 = fmaf(emb[s * D + j + 1], Wlot[(D + j + 1) * D + c], a1);
            a2 = fmaf(emb[s * D + j + 2], Wlot[(D + j + 2) * D + c], a2);
            a3 = fmaf(emb[s * D + j + 3], Wlot[(D + j + 3) * D + c], a3);
        }
        g_Msem[s * D + c] = (a0 + a1) + (a2 + a3);
    } else {
        for (int j = 0; j < D; j += 4) {
            a0 = fmaf(bgeo[j + 0], Wlot[(j + 0) * D + c], a0);
            a1 = fmaf(bgeo[j + 1], Wlot[(j + 1) * D + c], a1);
            a2 = fmaf(bgeo[j + 2], Wlot[(j + 2) * D + c], a2);
            a3 = fmaf(bgeo[j + 3], Wlot[(j + 3) * D + c], a3);
        }
        g_bias0[c] = blot[c] + (a0 + a1) + (a2 + a3);
    }
}

__global__ void pack_kernel(const float* __restrict__ W1,
                            const float* __restrict__ W2,
                            const float* __restrict__ W3)
{
    int l   = blockIdx.x >> 8;        // 0..2
    int kp2 = blockIdx.x & 255;       // 0..255
    int cp  = threadIdx.x;            // 0..127
    const float* W = (l == 0) ? W1 : (l == 1) ? W2 : W3;
    int k0 = 2 * kp2;                 // 0..510
    int c0 = 2 * cp;
    unsigned lo0 = __float_as_uint(W[k0 * D + c0]);
    unsigned hi0 = __float_as_uint(W[(k0 + 1) * D + c0]);
    unsigned lo1 = __float_as_uint(W[k0 * D + c0 + 1]);
    unsigned hi1 = __float_as_uint(W[(k0 + 1) * D + c0 + 1]);
    ulonglong2 v;
    v.x = (unsigned long long)lo0 | ((unsigned long long)hi0 << 32);
    v.y = (unsigned long long)lo1 | ((unsigned long long)hi1 << 32);
    g_Wp2[l][kp2 * 128 + cp] = v;
}

// ---------------------------------------------------------------------------
// One CTA per graph. 512 threads: tid = rg*128 + cp.
// Thread (rg, cp) owns cols {2cp, 2cp+1} for rows [8rg, 8rg+8).
// GEMM uses fma.rn.f32x2 with K-pair packing: even k in lo, odd k in hi,
// folded lo+hi at the end. acc = 16 u64 = 32 regs.
// ---------------------------------------------------------------------------
__global__ void __launch_bounds__(512, 1)
graph_kernel(const float* __restrict__ geometry,
             const int*   __restrict__ semantic,
             const int*   __restrict__ e_src,
             const int*   __restrict__ e_dst,
             const float* __restrict__ Wlot,
             const float* __restrict__ bmp1,
             const float* __restrict__ bmp2,
             const float* __restrict__ bmp3)
{
    extern __shared__ float smem[];
    float* sh_h  = smem;                  // NP*D = 8192
    float* sh_xa = sh_h + NP * D;         // NP*D = 8192
    float* smax  = sh_xa + NP * D;        // 4*D (per row-group partial max)
    float* s_geo = smax + 4 * D;          // NB*5
    float* s_inv = s_geo + NB * 5;        // NB
    int*   s_sem = (int*)(s_inv + NB);    // NB
    int*   s_cnt = s_sem + NB;            // NB
    int*   s_off = s_cnt + NB;            // NB+1
    int*   s_cur = s_off + NB + 1;        // NB
    int*   s_list = s_cur + NB;           // EG

    const int g   = blockIdx.x;
    const int tid = threadIdx.x;
    const int cp  = tid & 127;
    const int rg  = tid >> 7;
    const int c0  = 2 * cp;
    const int r0  = rg * RT;

    // ---- per-graph data, degrees, CSR ----
    for (int i = tid; i < NB * 5; i += 512) s_geo[i] = geometry[g * NB * 5 + i];
    if (tid < NB) { s_sem[tid] = semantic[g * NB + tid]; s_cnt[tid] = 0; }
    __syncthreads();
    if (tid < EG) {
        int d = e_dst[g * EG + tid] - g * NB;
        atomicAdd(&s_cnt[d], 1);
    }
    __syncthreads();
    if (tid == 0) {
        int a = 0;
        for (int i = 0; i < NB; i++) { s_off[i] = a; s_cur[i] = a; a += s_cnt[i]; }
        s_off[NB] = a;
    }
    if (tid < NB) s_inv[tid] = s_cnt[tid] ? 1.0f / (float)s_cnt[tid] : 0.0f;
    __syncthreads();
    if (tid < EG) {
        int s = e_src[g * EG + tid] - g * NB;
        int d = e_dst[g * EG + tid] - g * NB;
        int p = atomicAdd(&s_cur[d], 1);
        s_list[p] = s;
    }

    // ---- h0 = relu(geo@Mgeo + Msem[sem] + W_lot_pos + bias0), 2 cols x 8 rows
    {
        float2 mg[5];
        #pragma unroll
        for (int j = 0; j < 5; j++) mg[j] = *(const float2*)(g_Mgeo + j * D + c0);
        const float2 b0 = *(const float2*)(g_bias0 + c0);
        float2 pm = make_float2(0.f, 0.f);
        #pragma unroll
        for (int i = 0; i < RT; i++) {
            int n = r0 + i;
            float2 v = make_float2(0.f, 0.f);
            if (n < NB) {
                float2 wl = *(const float2*)(Wlot + (2 * D + n) * D + c0);
                float2 ms = *(const float2*)(g_Msem + s_sem[n] * D + c0);
                v = make_float2(b0.x + wl.x + ms.x, b0.y + wl.y + ms.y);
                #pragma unroll
                for (int j = 0; j < 5; j++) {
                    float ge = s_geo[n * 5 + j];
                    v.x = fmaf(ge, mg[j].x, v.x);
                    v.y = fmaf(ge, mg[j].y, v.y);
                }
                v.x = fmaxf(v.x, 0.f); v.y = fmaxf(v.y, 0.f);
            }
            *(float2*)(sh_h + n * D + c0) = v;
            pm.x = fmaxf(pm.x, v.x); pm.y = fmaxf(pm.y, v.y);
        }
        *(float2*)(smax + rg * D + c0) = pm;
    }
    __syncthreads();
    if (tid < D)
        g_gbuf[g * 1024 + 0 * D + tid] =
            fmaxf(fmaxf(smax[tid], smax[D + tid]),
                  fmaxf(smax[2 * D + tid], smax[3 * D + tid]));

    // ---- 3 message-passing layers ----
    const float* bms[3] = { bmp1, bmp2, bmp3 };

    for (int l = 0; l < 3; l++) {
        // gather: xa[n] = mean_{src in N(n)} h[src]
        #pragma unroll
        for (int i = 0; i < RT; i++) {
            int n = r0 + i;
            float2 a = make_float2(0.f, 0.f);
            if (n < NB) {
                int e1 = s_off[n + 1];
                for (int e = s_off[n]; e < e1; e++) {
                    float2 hv = *(const float2*)(sh_h + s_list[e] * D + c0);
                    a.x += hv.x; a.y += hv.y;
                }
                float inv = s_inv[n];
                a.x *= inv; a.y *= inv;
            }
            *(float2*)(sh_xa + n * D + c0) = a;
        }
        __syncthreads();

        // GEMM: C[n][c0..c0+1] = b + h[n]@W1 + xa[n]@W2  (f32x2, K-pair packed)
        const float2 bm = *(const float2*)(bms[l] + c0);
        unsigned long long acc[RT][2];
        #pragma unroll
        for (int i = 0; i < RT; i++) {
            acc[i][0] = (unsigned long long)__float_as_uint(bm.x);  // lo=bias, hi=0
            acc[i][1] = (unsigned long long)__float_as_uint(bm.y);
        }

        #pragma unroll
        for (int part = 0; part < 2; part++) {
            const float* A = (part ? sh_xa : sh_h) + r0 * D;
            const ulonglong2* Wb = g_Wp2[l] + part * 128 * 128 + cp;
            #pragma unroll 4
            for (int kpl = 0; kpl < 128; kpl += 2) {
                ulonglong2 w0 = Wb[(kpl + 0) * 128];
                ulonglong2 w1 = Wb[(kpl + 1) * 128];
                const float* Ak = A + 2 * kpl;
                #pragma unroll
                for (int i = 0; i < RT; i++) {
                    ulonglong2 hv = *reinterpret_cast<const ulonglong2*>(Ak + i * D);
                    FMA2(acc[i][0], hv.x, w0.x);
                    FMA2(acc[i][1], hv.x, w0.y);
                    FMA2(acc[i][0], hv.y, w1.x);
                    FMA2(acc[i][1], hv.y, w1.y);
                }
            }
        }
        __syncthreads();   // all reads of sh_h / sh_xa done

        float2 pm = make_float2(0.f, 0.f);
        #pragma unroll
        for (int i = 0; i < RT; i++) {
            int n = r0 + i;
            float2 v = make_float2(0.f, 0.f);
            if (n < NB && s_cnt[n]) {      // cnt=0 / padded -> exact 0
                float x = __uint_as_float((unsigned)acc[i][0])
                        + __uint_as_float((unsigned)(acc[i][0] >> 32));
                float y = __uint_as_float((unsigned)acc[i][1])
                        + __uint_as_float((unsigned)(acc[i][1] >> 32));
                v.x = fmaxf(x, 0.f);
                v.y = fmaxf(y, 0.f);
            }
            *(float2*)(sh_h + n * D + c0) = v;
            pm.x = fmaxf(pm.x, v.x); pm.y = fmaxf(pm.y, v.y);
        }
        *(float2*)(smax + rg * D + c0) = pm;
        __syncthreads();
        if (tid < D)
            g_gbuf[g * 1024 + (l + 1) * D + tid] =
                fmaxf(fmaxf(smax[tid], smax[D + tid]),
                      fmaxf(smax[2 * D + tid], smax[3 * D + tid]));
    }
}

// ---------------------------------------------------------------------------
// Readout: latent = g @ Wagg + b; mu/logvar = latent @ Wmu/Wvar + b.
// 32 graphs per CTA -> readout weights read 64x total instead of 2048x.
// ---------------------------------------------------------------------------
__global__ void __launch_bounds__(256)
aux_kernel(const float* __restrict__ Wagg, const float* __restrict__ bagg,
           const float* __restrict__ Wmu,  const float* __restrict__ bmu,
           const float* __restrict__ Wvar, const float* __restrict__ bvar,
           float* __restrict__ out)
{
    __shared__ float sh_lat[GAUX * D];
    const int c  = threadIdx.x;
    const int g0 = blockIdx.x * GAUX;

    float lat[GAUX];
    {
        float bg = bagg[c];
        #pragma unroll
        for (int i = 0; i < GAUX; i++) lat[i] = bg;
    }
    for (int k4 = 0; k4 < 4 * D; k4 += 4) {
        float w0 = Wagg[(k4 + 0) * D + c];
        float w1 = Wagg[(k4 + 1) * D + c];
        float w2 = Wagg[(k4 + 2) * D + c];
        float w3 = Wagg[(k4 + 3) * D + c];
        #pragma unroll 8
        for (int i = 0; i < GAUX; i++) {
            float4 gv = *(const float4*)(g_gbuf + (g0 + i) * 1024 + k4);
            lat[i] = fmaf(gv.x, w0, fmaf(gv.y, w1, fmaf(gv.z, w2, fmaf(gv.w, w3, lat[i]))));
        }
    }
    #pragma unroll
    for (int i = 0; i < GAUX; i++) sh_lat[i * D + c] = lat[i];
    __syncthreads();

    float mu[GAUX], lv[GAUX];
    {
        float bm_ = bmu[c], bv_ = bvar[c];
        #pragma unroll
        for (int i = 0; i < GAUX; i++) { mu[i] = bm_; lv[i] = bv_; }
    }
    for (int j4 = 0; j4 < D; j4 += 4) {
        float m0 = Wmu[(j4 + 0) * D + c],  m1 = Wmu[(j4 + 1) * D + c];
        float m2 = Wmu[(j4 + 2) * D + c],  m3 = Wmu[(j4 + 3) * D + c];
        float v0 = Wvar[(j4 + 0) * D + c], v1 = Wvar[(j4 + 1) * D + c];
        float v2 = Wvar[(j4 + 2) * D + c], v3 = Wvar[(j4 + 3) * D + c];
        #pragma unroll 8
        for (int i = 0; i < GAUX; i++) {
            float4 L = *(const float4*)(sh_lat + i * D + j4);
            mu[i] = fmaf(L.x, m0, fmaf(L.y, m1, fmaf(L.z, m2, fmaf(L.w, m3, mu[i]))));
            lv[i] = fmaf(L.x, v0, fmaf(L.y, v1, fmaf(L.z, v2, fmaf(L.w, v3, lv[i]))));
        }
    }
    #pragma unroll
    for (int i = 0; i < GAUX; i++) {
        out[(g0 + i) * D + c]          = mu[i];
        out[BG * D + (g0 + i) * D + c] = lv[i];
    }
}

// ---------------------------------------------------------------------------
extern "C" void kernel_launch(void* const* d_in, const int* in_sizes, int n_in,
                              void* d_out, int out_size)
{
    const float* geometry = (const float*)d_in[0];
    const int*   semantic = (const int*)d_in[1];
    const int*   eidx     = (const int*)d_in[2];
    const float* Wgeo = (const float*)d_in[4];
    const float* bgeo = (const float*)d_in[5];
    const float* emb  = (const float*)d_in[6];
    const float* Wlot = (const float*)d_in[7];
    const float* blot = (const float*)d_in[8];
    const float* Wmp1 = (const float*)d_in[9];
    const float* bmp1 = (const float*)d_in[10];
    const float* Wmp2 = (const float*)d_in[11];
    const float* bmp2 = (const float*)d_in[12];
    const float* Wmp3 = (const float*)d_in[13];
    const float* bmp3 = (const float*)d_in[14];
    const float* Wagg = (const float*)d_in[15];
    const float* bagg = (const float*)d_in[16];
    const float* Wmu  = (const float*)d_in[17];
    const float* bmu  = (const float*)d_in[18];
    const float* Wvar = (const float*)d_in[19];
    const float* bvar = (const float*)d_in[20];

    const int n_edges = in_sizes[2] / 2;
    const int* e_src = eidx;
    const int* e_dst = eidx + n_edges;

    pre_kernel<<<17, 256>>>(Wgeo, bgeo, emb, Wlot, blot);
    pack_kernel<<<3 * 256, 128>>>(Wmp1, Wmp2, Wmp3);

    size_t smem_bytes = (2 * NP * D + 4 * D + NB * 5 + NB) * sizeof(float)
                      + (3 * NB + 1 + EG) * sizeof(int) + 64;
    cudaFuncSetAttribute(graph_kernel, cudaFuncAttributeMaxDynamicSharedMemorySize,
                         (int)smem_bytes);

    graph_kernel<<<BG, 512, smem_bytes>>>(
        geometry, semantic, e_src, e_dst, Wlot, bmp1, bmp2, bmp3);

    aux_kernel<<<BG / GAUX, 256>>>(Wagg, bagg, Wmu, bmu, Wvar, bvar, (float*)d_out);
}

// round 11
// speedup vs baseline: 1.2005x; 1.2005x over previous
#include <cuda_runtime.h>

#define D     256
#define NB    30
#define NP    32      // padded rows
#define RT    8       // rows per thread (4 row-groups)
#define EG    240
#define BG    2048
#define GAUX  8       // graphs per aux CTA (small => accumulators stay in regs)

// fused fp32x2 FMA: acc.lo += a.lo*b.lo; acc.hi += a.hi*b.hi
#define FMA2(d, a, b) \
    asm("fma.rn.f32x2 %0, %1, %2, %0;" : "+l"(d) : "l"(a), "l"(b))

// Precomputed folded input-MLP matrices
__device__ float g_Mgeo[5 * D];
__device__ float g_Msem[11 * D];
__device__ float g_bias0[D];
// pooled per-graph features [g][4*256]
__device__ float g_gbuf[BG * 4 * D];
// K-pair + col-pair packed message weights:
//   g_Wp2[l][kp2*128 + cp] = { (W[k0][2cp],W[k0+1][2cp]), (W[k0][2cp+1],W[k0+1][2cp+1]) }
__device__ ulonglong2 g_Wp2[3][256 * 128];

// ---------------------------------------------------------------------------
__global__ void pre_kernel(const float* __restrict__ Wgeo,
                           const float* __restrict__ bgeo,
                           const float* __restrict__ emb,
                           const float* __restrict__ Wlot,
                           const float* __restrict__ blot)
{
    int c = threadIdx.x;
    int r = blockIdx.x;
    float a0 = 0.f, a1 = 0.f, a2 = 0.f, a3 = 0.f;
    if (r < 5) {
        for (int j = 0; j < D; j += 4) {
            a0 = fmaf(Wgeo[r * D + j + 0], Wlot[(j + 0) * D + c], a0);
            a1 = fmaf(Wgeo[r * D + j + 1], Wlot[(j + 1) * D + c], a1);
            a2 = fmaf(Wgeo[r * D + j + 2], Wlot[(j + 2) * D + c], a2);
            a3 = fmaf(Wgeo[r * D + j + 3], Wlot[(j + 3) * D + c], a3);
        }
        g_Mgeo[r * D + c] = (a0 + a1) + (a2 + a3);
    } else if (r < 16) {
        int s = r - 5;
        for (int j = 0; j < D; j += 4) {
            a0 = fmaf(emb[s * D + j + 0], Wlot[(D + j + 0) * D + c], a0);
            a1 = fmaf(emb[s * D + j + 1], Wlot[(D + j + 1) * D + c], a1);
            a2 = fmaf(emb[s * D + j + 2], Wlot[(D + j + 2) * D + c], a2);
            a3 = fmaf(emb[s * D + j + 3], Wlot[(D + j + 3) * D + c], a3);
        }
        g_Msem[s * D + c] = (a0 + a1) + (a2 + a3);
    } else {
        for (int j = 0; j < D; j += 4) {
            a0 = fmaf(bgeo[j + 0], Wlot[(j + 0) * D + c], a0);
            a1 = fmaf(bgeo[j + 1], Wlot[(j + 1) * D + c], a1);
            a2 = fmaf(bgeo[j + 2], Wlot[(j + 2) * D + c], a2);
            a3 = fmaf(bgeo[j + 3], Wlot[(j + 3) * D + c], a3);
        }
        g_bias0[c] = blot[c] + (a0 + a1) + (a2 + a3);
    }
}

__global__ void pack_kernel(const float* __restrict__ W1,
                            const float* __restrict__ W2,
                            const float* __restrict__ W3)
{
    int l   = blockIdx.x >> 8;        // 0..2
    int kp2 = blockIdx.x & 255;       // 0..255
    int cp  = threadIdx.x;            // 0..127
    const float* W = (l == 0) ? W1 : (l == 1) ? W2 : W3;
    int k0 = 2 * kp2;
    int c0 = 2 * cp;
    unsigned lo0 = __float_as_uint(W[k0 * D + c0]);
    unsigned hi0 = __float_as_uint(W[(k0 + 1) * D + c0]);
    unsigned lo1 = __float_as_uint(W[k0 * D + c0 + 1]);
    unsigned hi1 = __float_as_uint(W[(k0 + 1) * D + c0 + 1]);
    ulonglong2 v;
    v.x = (unsigned long long)lo0 | ((unsigned long long)hi0 << 32);
    v.y = (unsigned long long)lo1 | ((unsigned long long)hi1 << 32);
    g_Wp2[l][kp2 * 128 + cp] = v;
}

// ---------------------------------------------------------------------------
// One CTA per graph. 512 threads: tid = rg*128 + cp.
// Thread (rg, cp) owns cols {2cp, 2cp+1} for rows [8rg, 8rg+8).
// GEMM uses fma.rn.f32x2 with K-pair packing (lo=even k, hi=odd k).
// ---------------------------------------------------------------------------
__global__ void __launch_bounds__(512, 1)
graph_kernel(const float* __restrict__ geometry,
             const int*   __restrict__ semantic,
             const int*   __restrict__ e_src,
             const int*   __restrict__ e_dst,
             const float* __restrict__ Wlot,
             const float* __restrict__ bmp1,
             const float* __restrict__ bmp2,
             const float* __restrict__ bmp3)
{
    extern __shared__ float smem[];
    float* sh_h  = smem;                  // NP*D = 8192
    float* sh_xa = sh_h + NP * D;         // NP*D = 8192
    float* smax  = sh_xa + NP * D;        // 4*D
    float* s_geo = smax + 4 * D;          // NB*5
    float* s_inv = s_geo + NB * 5;        // NB
    int*   s_sem = (int*)(s_inv + NB);    // NB
    int*   s_cnt = s_sem + NB;            // NB
    int*   s_off = s_cnt + NB;            // NB+1
    int*   s_cur = s_off + NB + 1;        // NB
    int*   s_list = s_cur + NB;           // EG

    const int g   = blockIdx.x;
    const int tid = threadIdx.x;
    const int cp  = tid & 127;
    const int rg  = tid >> 7;
    const int c0  = 2 * cp;
    const int r0  = rg * RT;

    // ---- per-graph data, degrees, CSR ----
    for (int i = tid; i < NB * 5; i += 512) s_geo[i] = geometry[g * NB * 5 + i];
    if (tid < NB) { s_sem[tid] = semantic[g * NB + tid]; s_cnt[tid] = 0; }
    __syncthreads();
    if (tid < EG) {
        int d = e_dst[g * EG + tid] - g * NB;
        atomicAdd(&s_cnt[d], 1);
    }
    __syncthreads();
    if (tid == 0) {
        int a = 0;
        for (int i = 0; i < NB; i++) { s_off[i] = a; s_cur[i] = a; a += s_cnt[i]; }
        s_off[NB] = a;
    }
    if (tid < NB) s_inv[tid] = s_cnt[tid] ? 1.0f / (float)s_cnt[tid] : 0.0f;
    __syncthreads();
    if (tid < EG) {
        int s = e_src[g * EG + tid] - g * NB;
        int d = e_dst[g * EG + tid] - g * NB;
        int p = atomicAdd(&s_cur[d], 1);
        s_list[p] = s;
    }

    // ---- h0 ----
    {
        float2 mg[5];
        #pragma unroll
        for (int j = 0; j < 5; j++) mg[j] = *(const float2*)(g_Mgeo + j * D + c0);
        const float2 b0 = *(const float2*)(g_bias0 + c0);
        float2 pm = make_float2(0.f, 0.f);
        #pragma unroll
        for (int i = 0; i < RT; i++) {
            int n = r0 + i;
            float2 v = make_float2(0.f, 0.f);
            if (n < NB) {
                float2 wl = *(const float2*)(Wlot + (2 * D + n) * D + c0);
                float2 ms = *(const float2*)(g_Msem + s_sem[n] * D + c0);
                v = make_float2(b0.x + wl.x + ms.x, b0.y + wl.y + ms.y);
                #pragma unroll
                for (int j = 0; j < 5; j++) {
                    float ge = s_geo[n * 5 + j];
                    v.x = fmaf(ge, mg[j].x, v.x);
                    v.y = fmaf(ge, mg[j].y, v.y);
                }
                v.x = fmaxf(v.x, 0.f); v.y = fmaxf(v.y, 0.f);
            }
            *(float2*)(sh_h + n * D + c0) = v;
            pm.x = fmaxf(pm.x, v.x); pm.y = fmaxf(pm.y, v.y);
        }
        *(float2*)(smax + rg * D + c0) = pm;
    }
    __syncthreads();
    if (tid < D)
        g_gbuf[g * 1024 + 0 * D + tid] =
            fmaxf(fmaxf(smax[tid], smax[D + tid]),
                  fmaxf(smax[2 * D + tid], smax[3 * D + tid]));

    // ---- 3 message-passing layers ----
    const float* bms[3] = { bmp1, bmp2, bmp3 };

    for (int l = 0; l < 3; l++) {
        // gather
        #pragma unroll
        for (int i = 0; i < RT; i++) {
            int n = r0 + i;
            float2 a = make_float2(0.f, 0.f);
            if (n < NB) {
                int e1 = s_off[n + 1];
                for (int e = s_off[n]; e < e1; e++) {
                    float2 hv = *(const float2*)(sh_h + s_list[e] * D + c0);
                    a.x += hv.x; a.y += hv.y;
                }
                float inv = s_inv[n];
                a.x *= inv; a.y *= inv;
            }
            *(float2*)(sh_xa + n * D + c0) = a;
        }
        __syncthreads();

        // GEMM (f32x2, K-pair packed)
        const float2 bm = *(const float2*)(bms[l] + c0);
        unsigned long long acc[RT][2];
        #pragma unroll
        for (int i = 0; i < RT; i++) {
            acc[i][0] = (unsigned long long)__float_as_uint(bm.x);
            acc[i][1] = (unsigned long long)__float_as_uint(bm.y);
        }

        #pragma unroll
        for (int part = 0; part < 2; part++) {
            const float* A = (part ? sh_xa : sh_h) + r0 * D;
            const ulonglong2* Wb = g_Wp2[l] + part * 128 * 128 + cp;
            #pragma unroll 4
            for (int kpl = 0; kpl < 128; kpl += 2) {
                ulonglong2 w0 = Wb[(kpl + 0) * 128];
                ulonglong2 w1 = Wb[(kpl + 1) * 128];
                const float* Ak = A + 2 * kpl;
                #pragma unroll
                for (int i = 0; i < RT; i++) {
                    ulonglong2 hv = *reinterpret_cast<const ulonglong2*>(Ak + i * D);
                    FMA2(acc[i][0], hv.x, w0.x);
                    FMA2(acc[i][1], hv.x, w0.y);
                    FMA2(acc[i][0], hv.y, w1.x);
                    FMA2(acc[i][1], hv.y, w1.y);
                }
            }
        }
        __syncthreads();

        float2 pm = make_float2(0.f, 0.f);
        #pragma unroll
        for (int i = 0; i < RT; i++) {
            int n = r0 + i;
            float2 v = make_float2(0.f, 0.f);
            if (n < NB && s_cnt[n]) {      // cnt=0 / padded -> exact 0
                float x = __uint_as_float((unsigned)acc[i][0])
                        + __uint_as_float((unsigned)(acc[i][0] >> 32));
                float y = __uint_as_float((unsigned)acc[i][1])
                        + __uint_as_float((unsigned)(acc[i][1] >> 32));
                v.x = fmaxf(x, 0.f);
                v.y = fmaxf(y, 0.f);
            }
            *(float2*)(sh_h + n * D + c0) = v;
            pm.x = fmaxf(pm.x, v.x); pm.y = fmaxf(pm.y, v.y);
        }
        *(float2*)(smax + rg * D + c0) = pm;
        __syncthreads();
        if (tid < D)
            g_gbuf[g * 1024 + (l + 1) * D + tid] =
                fmaxf(fmaxf(smax[tid], smax[D + tid]),
                      fmaxf(smax[2 * D + tid], smax[3 * D + tid]));
    }
}

// ---------------------------------------------------------------------------
// Readout: latent = g @ Wagg + b; mu/logvar = latent @ Wmu/Wvar + b.
// GAUX=8, grid=256: accumulators (8x3 floats) fully unrolled => pure
// registers (the R9 version used GAUX=32 arrays with partial unroll, which
// ptxas demoted to local memory -> 608 us on 64 idle-ish CTAs).
// ---------------------------------------------------------------------------
__global__ void __launch_bounds__(256)
aux_kernel(const float* __restrict__ Wagg, const float* __restrict__ bagg,
           const float* __restrict__ Wmu,  const float* __restrict__ bmu,
           const float* __restrict__ Wvar, const float* __restrict__ bvar,
           float* __restrict__ out)
{
    __shared__ float sh_lat[GAUX * D];
    const int c  = threadIdx.x;
    const int g0 = blockIdx.x * GAUX;

    float lat[GAUX];
    {
        float bg = bagg[c];
        #pragma unroll
        for (int i = 0; i < GAUX; i++) lat[i] = bg;
    }
    for (int k4 = 0; k4 < 4 * D; k4 += 4) {
        float w0 = Wagg[(k4 + 0) * D + c];
        float w1 = Wagg[(k4 + 1) * D + c];
        float w2 = Wagg[(k4 + 2) * D + c];
        float w3 = Wagg[(k4 + 3) * D + c];
        #pragma unroll
        for (int i = 0; i < GAUX; i++) {
            float4 gv = *(const float4*)(g_gbuf + (g0 + i) * 1024 + k4);
            lat[i] = fmaf(gv.x, w0, fmaf(gv.y, w1, fmaf(gv.z, w2, fmaf(gv.w, w3, lat[i]))));
        }
    }
    #pragma unroll
    for (int i = 0; i < GAUX; i++) sh_lat[i * D + c] = lat[i];
    __syncthreads();

    float mu[GAUX], lv[GAUX];
    {
        float bm_ = bmu[c], bv_ = bvar[c];
        #pragma unroll
        for (int i = 0; i < GAUX; i++) { mu[i] = bm_; lv[i] = bv_; }
    }
    for (int j4 = 0; j4 < D; j4 += 4) {
        float m0 = Wmu[(j4 + 0) * D + c],  m1 = Wmu[(j4 + 1) * D + c];
        float m2 = Wmu[(j4 + 2) * D + c],  m3 = Wmu[(j4 + 3) * D + c];
        float v0 = Wvar[(j4 + 0) * D + c], v1 = Wvar[(j4 + 1) * D + c];
        float v2 = Wvar[(j4 + 2) * D + c], v3 = Wvar[(j4 + 3) * D + c];
        #pragma unroll
        for (int i = 0; i < GAUX; i++) {
            float4 L = *(const float4*)(sh_lat + i * D + j4);
            mu[i] = fmaf(L.x, m0, fmaf(L.y, m1, fmaf(L.z, m2, fmaf(L.w, m3, mu[i]))));
            lv[i] = fmaf(L.x, v0, fmaf(L.y, v1, fmaf(L.z, v2, fmaf(L.w, v3, lv[i]))));
        }
    }
    #pragma unroll
    for (int i = 0; i < GAUX; i++) {
        out[(g0 + i) * D + c]          = mu[i];
        out[BG * D + (g0 + i) * D + c] = lv[i];
    }
}

// ---------------------------------------------------------------------------
extern "C" void kernel_launch(void* const* d_in, const int* in_sizes, int n_in,
                              void* d_out, int out_size)
{
    const float* geometry = (const float*)d_in[0];
    const int*   semantic = (const int*)d_in[1];
    const int*   eidx     = (const int*)d_in[2];
    const float* Wgeo = (const float*)d_in[4];
    const float* bgeo = (const float*)d_in[5];
    const float* emb  = (const float*)d_in[6];
    const float* Wlot = (const float*)d_in[7];
    const float* blot = (const float*)d_in[8];
    const float* Wmp1 = (const float*)d_in[9];
    const float* bmp1 = (const float*)d_in[10];
    const float* Wmp2 = (const float*)d_in[11];
    const float* bmp2 = (const float*)d_in[12];
    const float* Wmp3 = (const float*)d_in[13];
    const float* bmp3 = (const float*)d_in[14];
    const float* Wagg = (const float*)d_in[15];
    const float* bagg = (const float*)d_in[16];
    const float* Wmu  = (const float*)d_in[17];
    const float* bmu  = (const float*)d_in[18];
    const float* Wvar = (const float*)d_in[19];
    const float* bvar = (const float*)d_in[20];

    const int n_edges = in_sizes[2] / 2;
    const int* e_src = eidx;
    const int* e_dst = eidx + n_edges;

    pre_kernel<<<17, 256>>>(Wgeo, bgeo, emb, Wlot, blot);
    pack_kernel<<<3 * 256, 128>>>(Wmp1, Wmp2, Wmp3);

    size_t smem_bytes = (2 * NP * D + 4 * D + NB * 5 + NB) * sizeof(float)
                      + (3 * NB + 1 + EG) * sizeof(int) + 64;
    cudaFuncSetAttribute(graph_kernel, cudaFuncAttributeMaxDynamicSharedMemorySize,
                         (int)smem_bytes);

    graph_kernel<<<BG, 512, smem_bytes>>>(
        geometry, semantic, e_src, e_dst, Wlot, bmp1, bmp2, bmp3);

    aux_kernel<<<BG / GAUX, 256>>>(Wagg, bagg, Wmu, bmu, Wvar, bvar, (float*)d_out);
}

// round 13
// speedup vs baseline: 1.3134x; 1.0941x over previous
#include <cuda_runtime.h>

#define D     256
#define NB    30
#define NP    32      // padded rows
#define RT    8       // rows per thread (4 row-groups)
#define EG    240
#define BG    2048
#define GAUX  8       // graphs per aux CTA

// fused fp32x2 FMA: acc.lo += a.lo*b.lo; acc.hi += a.hi*b.hi
#define FMA2(d, a, b) \
    asm("fma.rn.f32x2 %0, %1, %2, %0;" : "+l"(d) : "l"(a), "l"(b))

// Precomputed folded input-MLP matrices
__device__ float g_Mgeo[5 * D];
__device__ float g_Msem[11 * D];
__device__ float g_bias0[D];
// pooled per-graph features [g][4*256]
__device__ float g_gbuf[BG * 4 * D];
// K-pair + col-pair packed message weights:
//   g_Wp2[l][kp2*128 + cp] = { (W[k0][2cp],W[k0+1][2cp]), (W[k0][2cp+1],W[k0+1][2cp+1]) }
__device__ ulonglong2 g_Wp2[3][256 * 128];

// ---------------------------------------------------------------------------
// Merged init: blocks 0..16 = folded input-MLP precompute; blocks 17..784 =
// message-weight packing (one (layer, k-pair-pair) per block, 128 lanes).
// ---------------------------------------------------------------------------
__global__ void init_kernel(const float* __restrict__ Wgeo,
                            const float* __restrict__ bgeo,
                            const float* __restrict__ emb,
                            const float* __restrict__ Wlot,
                            const float* __restrict__ blot,
                            const float* __restrict__ W1,
                            const float* __restrict__ W2,
                            const float* __restrict__ W3)
{
    int b = blockIdx.x;
    if (b < 17) {
        int c = threadIdx.x;
        int r = b;
        float a0 = 0.f, a1 = 0.f, a2 = 0.f, a3 = 0.f;
        if (r < 5) {
            for (int j = 0; j < D; j += 4) {
                a0 = fmaf(Wgeo[r * D + j + 0], Wlot[(j + 0) * D + c], a0);
                a1 = fmaf(Wgeo[r * D + j + 1], Wlot[(j + 1) * D + c], a1);
                a2 = fmaf(Wgeo[r * D + j + 2], Wlot[(j + 2) * D + c], a2);
                a3 = fmaf(Wgeo[r * D + j + 3], Wlot[(j + 3) * D + c], a3);
            }
            g_Mgeo[r * D + c] = (a0 + a1) + (a2 + a3);
        } else if (r < 16) {
            int s = r - 5;
            for (int j = 0; j < D; j += 4) {
                a0 = fmaf(emb[s * D + j + 0], Wlot[(D + j + 0) * D + c], a0);
                a1 = fmaf(emb[s * D + j + 1], Wlot[(D + j + 1) * D + c], a1);
                a2 = fmaf(emb[s * D + j + 2], Wlot[(D + j + 2) * D + c], a2);
                a3 = fmaf(emb[s * D + j + 3], Wlot[(D + j + 3) * D + c], a3);
            }
            g_Msem[s * D + c] = (a0 + a1) + (a2 + a3);
        } else {
            for (int j = 0; j < D; j += 4) {
                a0 = fmaf(bgeo[j + 0], Wlot[(j + 0) * D + c], a0);
                a1 = fmaf(bgeo[j + 1], Wlot[(j + 1) * D + c], a1);
                a2 = fmaf(bgeo[j + 2], Wlot[(j + 2) * D + c], a2);
                a3 = fmaf(bgeo[j + 3], Wlot[(j + 3) * D + c], a3);
            }
            g_bias0[c] = blot[c] + (a0 + a1) + (a2 + a3);
        }
    } else if (threadIdx.x < 128) {
        int bb  = b - 17;
        int l   = bb >> 8;            // 0..2
        int kp2 = bb & 255;           // 0..255
        int cp  = threadIdx.x;        // 0..127
        const float* W = (l == 0) ? W1 : (l == 1) ? W2 : W3;
        int k0 = 2 * kp2;
        int c0 = 2 * cp;
        unsigned lo0 = __float_as_uint(W[k0 * D + c0]);
        unsigned hi0 = __float_as_uint(W[(k0 + 1) * D + c0]);
        unsigned lo1 = __float_as_uint(W[k0 * D + c0 + 1]);
        unsigned hi1 = __float_as_uint(W[(k0 + 1) * D + c0 + 1]);
        ulonglong2 v;
        v.x = (unsigned long long)lo0 | ((unsigned long long)hi0 << 32);
        v.y = (unsigned long long)lo1 | ((unsigned long long)hi1 << 32);
        g_Wp2[l][kp2 * 128 + cp] = v;
    }
}

// ---------------------------------------------------------------------------
// One CTA per graph. 512 threads: tid = rg*128 + cp.
// Thread (rg, cp) owns cols {2cp, 2cp+1} for rows [8rg, 8rg+8).
// GEMM uses fma.rn.f32x2 with K-pair packing (lo=even k, hi=odd k).
// ---------------------------------------------------------------------------
__global__ void __launch_bounds__(512, 1)
graph_kernel(const float* __restrict__ geometry,
             const int*   __restrict__ semantic,
             const int*   __restrict__ e_src,
             const int*   __restrict__ e_dst,
             const float* __restrict__ Wlot,
             const float* __restrict__ bmp1,
             const float* __restrict__ bmp2,
             const float* __restrict__ bmp3)
{
    extern __shared__ float smem[];
    float* sh_h  = smem;                  // NP*D = 8192
    float* sh_xa = sh_h + NP * D;         // NP*D = 8192
    float* smax  = sh_xa + NP * D;        // 4*D
    float* s_geo = smax + 4 * D;          // NB*5
    float* s_inv = s_geo + NB * 5;        // NB
    int*   s_sem = (int*)(s_inv + NB);    // NB
    int*   s_cnt = s_sem + NB;            // NB
    int*   s_off = s_cnt + NB;            // NB+1
    int*   s_cur = s_off + NB + 1;        // NB
    int*   s_list = s_cur + NB;           // EG

    const int g   = blockIdx.x;
    const int tid = threadIdx.x;
    const int cp  = tid & 127;
    const int rg  = tid >> 7;
    const int c0  = 2 * cp;
    const int r0  = rg * RT;

    // ---- per-graph data, degrees, CSR ----
    for (int i = tid; i < NB * 5; i += 512) s_geo[i] = geometry[g * NB * 5 + i];
    if (tid < NB) { s_sem[tid] = semantic[g * NB + tid]; s_cnt[tid] = 0; }
    __syncthreads();
    if (tid < EG) {
        int d = e_dst[g * EG + tid] - g * NB;
        atomicAdd(&s_cnt[d], 1);
    }
    __syncthreads();
    if (tid == 0) {
        int a = 0;
        for (int i = 0; i < NB; i++) { s_off[i] = a; s_cur[i] = a; a += s_cnt[i]; }
        s_off[NB] = a;
    }
    if (tid < NB) s_inv[tid] = s_cnt[tid] ? 1.0f / (float)s_cnt[tid] : 0.0f;
    __syncthreads();
    if (tid < EG) {
        int s = e_src[g * EG + tid] - g * NB;
        int d = e_dst[g * EG + tid] - g * NB;
        int p = atomicAdd(&s_cur[d], 1);
        s_list[p] = s;
    }

    // ---- h0 ----
    {
        float2 mg[5];
        #pragma unroll
        for (int j = 0; j < 5; j++) mg[j] = *(const float2*)(g_Mgeo + j * D + c0);
        const float2 b0 = *(const float2*)(g_bias0 + c0);
        float2 pm = make_float2(0.f, 0.f);
        #pragma unroll
        for (int i = 0; i < RT; i++) {
            int n = r0 + i;
            float2 v = make_float2(0.f, 0.f);
            if (n < NB) {
                float2 wl = *(const float2*)(Wlot + (2 * D + n) * D + c0);
                float2 ms = *(const float2*)(g_Msem + s_sem[n] * D + c0);
                v = make_float2(b0.x + wl.x + ms.x, b0.y + wl.y + ms.y);
                #pragma unroll
                for (int j = 0; j < 5; j++) {
                    float ge = s_geo[n * 5 + j];
                    v.x = fmaf(ge, mg[j].x, v.x);
                    v.y = fmaf(ge, mg[j].y, v.y);
                }
                v.x = fmaxf(v.x, 0.f); v.y = fmaxf(v.y, 0.f);
            }
            *(float2*)(sh_h + n * D + c0) = v;
            pm.x = fmaxf(pm.x, v.x); pm.y = fmaxf(pm.y, v.y);
        }
        *(float2*)(smax + rg * D + c0) = pm;
    }
    __syncthreads();
    if (tid < D)
        g_gbuf[g * 1024 + 0 * D + tid] =
            fmaxf(fmaxf(smax[tid], smax[D + tid]),
                  fmaxf(smax[2 * D + tid], smax[3 * D + tid]));

    // ---- 3 message-passing layers ----
    const float* bms[3] = { bmp1, bmp2, bmp3 };

    for (int l = 0; l < 3; l++) {
        // gather
        #pragma unroll
        for (int i = 0; i < RT; i++) {
            int n = r0 + i;
            float2 a = make_float2(0.f, 0.f);
            if (n < NB) {
                int e1 = s_off[n + 1];
                for (int e = s_off[n]; e < e1; e++) {
                    float2 hv = *(const float2*)(sh_h + s_list[e] * D + c0);
                    a.x += hv.x; a.y += hv.y;
                }
                float inv = s_inv[n];
                a.x *= inv; a.y *= inv;
            }
            *(float2*)(sh_xa + n * D + c0) = a;
        }
        __syncthreads();

        // GEMM (f32x2, K-pair packed)
        const float2 bm = *(const float2*)(bms[l] + c0);
        unsigned long long acc[RT][2];
        #pragma unroll
        for (int i = 0; i < RT; i++) {
            acc[i][0] = (unsigned long long)__float_as_uint(bm.x);
            acc[i][1] = (unsigned long long)__float_as_uint(bm.y);
        }

        #pragma unroll
        for (int part = 0; part < 2; part++) {
            const float* A = (part ? sh_xa : sh_h) + r0 * D;
            const ulonglong2* Wb = g_Wp2[l] + part * 128 * 128 + cp;
            #pragma unroll 4
            for (int kpl = 0; kpl < 128; kpl += 2) {
                ulonglong2 w0 = Wb[(kpl + 0) * 128];
                ulonglong2 w1 = Wb[(kpl + 1) * 128];
                const float* Ak = A + 2 * kpl;
                #pragma unroll
                for (int i = 0; i < RT; i++) {
                    ulonglong2 hv = *reinterpret_cast<const ulonglong2*>(Ak + i * D);
                    FMA2(acc[i][0], hv.x, w0.x);
                    FMA2(acc[i][1], hv.x, w0.y);
                    FMA2(acc[i][0], hv.y, w1.x);
                    FMA2(acc[i][1], hv.y, w1.y);
                }
            }
        }
        __syncthreads();

        float2 pm = make_float2(0.f, 0.f);
        #pragma unroll
        for (int i = 0; i < RT; i++) {
            int n = r0 + i;
            float2 v = make_float2(0.f, 0.f);
            if (n < NB && s_cnt[n]) {      // cnt=0 / padded -> exact 0
                float x = __uint_as_float((unsigned)acc[i][0])
                        + __uint_as_float((unsigned)(acc[i][0] >> 32));
                float y = __uint_as_float((unsigned)acc[i][1])
                        + __uint_as_float((unsigned)(acc[i][1] >> 32));
                v.x = fmaxf(x, 0.f);
                v.y = fmaxf(y, 0.f);
            }
            *(float2*)(sh_h + n * D + c0) = v;
            pm.x = fmaxf(pm.x, v.x); pm.y = fmaxf(pm.y, v.y);
        }
        *(float2*)(smax + rg * D + c0) = pm;
        __syncthreads();
        if (tid < D)
            g_gbuf[g * 1024 + (l + 1) * D + tid] =
                fmaxf(fmaxf(smax[tid], smax[D + tid]),
                      fmaxf(smax[2 * D + tid], smax[3 * D + tid]));
    }
}

// ---------------------------------------------------------------------------
// Readout: latent = g @ Wagg + b; mu/logvar = latent @ Wmu/Wvar + b.
// The 8 graphs' pooled vectors (32 KB) are staged into smem ONCE with a
// coalesced bulk copy (full-MLP latency paid once); the k-loop then reads
// broadcast LDS while W streams coalesced from L2.
// ---------------------------------------------------------------------------
__global__ void __launch_bounds__(256)
aux_kernel(const float* __restrict__ Wagg, const float* __restrict__ bagg,
           const float* __restrict__ Wmu,  const float* __restrict__ bmu,
           const float* __restrict__ Wvar, const float* __restrict__ bvar,
           float* __restrict__ out)
{
    __shared__ float sh_g[GAUX * 1024];    // 32 KB
    __shared__ float sh_lat[GAUX * D];     // 8 KB
    const int c  = threadIdx.x;
    const int g0 = blockIdx.x * GAUX;

    // stage pooled vectors (coalesced, 8 float4 per thread)
    {
        const float4* src = (const float4*)(g_gbuf + g0 * 1024);
        float4* dst = (float4*)sh_g;
        #pragma unroll
        for (int i = 0; i < GAUX * 1024 / 4 / 256; i++)
            dst[i * 256 + c] = src[i * 256 + c];
    }
    __syncthreads();

    float lat[GAUX];
    {
        float bg = bagg[c];
        #pragma unroll
        for (int i = 0; i < GAUX; i++) lat[i] = bg;
    }
    for (int k4 = 0; k4 < 4 * D; k4 += 4) {
        float w0 = Wagg[(k4 + 0) * D + c];
        float w1 = Wagg[(k4 + 1) * D + c];
        float w2 = Wagg[(k4 + 2) * D + c];
        float w3 = Wagg[(k4 + 3) * D + c];
        #pragma unroll
        for (int i = 0; i < GAUX; i++) {
            float4 gv = *(const float4*)(sh_g + i * 1024 + k4);
            lat[i] = fmaf(gv.x, w0, fmaf(gv.y, w1, fmaf(gv.z, w2, fmaf(gv.w, w3, lat[i]))));
        }
    }
    __syncthreads();
    #pragma unroll
    for (int i = 0; i < GAUX; i++) sh_lat[i * D + c] = lat[i];
    __syncthreads();

    float mu[GAUX], lv[GAUX];
    {
        float bm_ = bmu[c], bv_ = bvar[c];
        #pragma unroll
        for (int i = 0; i < GAUX; i++) { mu[i] = bm_; lv[i] = bv_; }
    }
    for (int j4 = 0; j4 < D; j4 += 4) {
        float m0 = Wmu[(j4 + 0) * D + c],  m1 = Wmu[(j4 + 1) * D + c];
        float m2 = Wmu[(j4 + 2) * D + c],  m3 = Wmu[(j4 + 3) * D + c];
        float v0 = Wvar[(j4 + 0) * D + c], v1 = Wvar[(j4 + 1) * D + c];
        float v2 = Wvar[(j4 + 2) * D + c], v3 = Wvar[(j4 + 3) * D + c];
        #pragma unroll
        for (int i = 0; i < GAUX; i++) {
            float4 L = *(const float4*)(sh_lat + i * D + j4);
            mu[i] = fmaf(L.x, m0, fmaf(L.y, m1, fmaf(L.z, m2, fmaf(L.w, m3, mu[i]))));
            lv[i] = fmaf(L.x, v0, fmaf(L.y, v1, fmaf(L.z, v2, fmaf(L.w, v3, lv[i]))));
        }
    }
    #pragma unroll
    for (int i = 0; i < GAUX; i++) {
        out[(g0 + i) * D + c]          = mu[i];
        out[BG * D + (g0 + i) * D + c] = lv[i];
    }
}

// ---------------------------------------------------------------------------
extern "C" void kernel_launch(void* const* d_in, const int* in_sizes, int n_in,
                              void* d_out, int out_size)
{
    const float* geometry = (const float*)d_in[0];
    const int*   semantic = (const int*)d_in[1];
    const int*   eidx     = (const int*)d_in[2];
    const float* Wgeo = (const float*)d_in[4];
    const float* bgeo = (const float*)d_in[5];
    const float* emb  = (const float*)d_in[6];
    const float* Wlot = (const float*)d_in[7];
    const float* blot = (const float*)d_in[8];
    const float* Wmp1 = (const float*)d_in[9];
    const float* bmp1 = (const float*)d_in[10];
    const float* Wmp2 = (const float*)d_in[11];
    const float* bmp2 = (const float*)d_in[12];
    const float* Wmp3 = (const float*)d_in[13];
    const float* bmp3 = (const float*)d_in[14];
    const float* Wagg = (const float*)d_in[15];
    const float* bagg = (const float*)d_in[16];
    const float* Wmu  = (const float*)d_in[17];
    const float* bmu  = (const float*)d_in[18];
    const float* Wvar = (const float*)d_in[19];
    const float* bvar = (const float*)d_in[20];

    const int n_edges = in_sizes[2] / 2;
    const int* e_src = eidx;
    const int* e_dst = eidx + n_edges;

    init_kernel<<<17 + 3 * 256, 256>>>(Wgeo, bgeo, emb, Wlot, blot,
                                       Wmp1, Wmp2, Wmp3);

    size_t smem_bytes = (2 * NP * D + 4 * D + NB * 5 + NB) * sizeof(float)
                      + (3 * NB + 1 + EG) * sizeof(int) + 64;
    cudaFuncSetAttribute(graph_kernel, cudaFuncAttributeMaxDynamicSharedMemorySize,
                         (int)smem_bytes);

    graph_kernel<<<BG, 512, smem_bytes>>>(
        geometry, semantic, e_src, e_dst, Wlot, bmp1, bmp2, bmp3);

    aux_kernel<<<BG / GAUX, 256>>>(Wagg, bagg, Wmu, bmu, Wvar, bvar, (float*)d_out);
}

// round 14
// speedup vs baseline: 1.3379x; 1.0187x over previous
#include <cuda_runtime.h>

#define D     256
#define NB    30
#define NP    32      // padded rows
#define RT    16      // rows per thread (2 row-groups)
#define EG    240
#define BG    2048
#define GAUX  8       // graphs per aux CTA

// fused fp32x2 FMA: acc.lo += a.lo*b.lo; acc.hi += a.hi*b.hi
#define FMA2(d, a, b) \
    asm("fma.rn.f32x2 %0, %1, %2, %0;" : "+l"(d) : "l"(a), "l"(b))

// Precomputed folded input-MLP matrices
__device__ float g_Mgeo[5 * D];
__device__ float g_Msem[11 * D];
__device__ float g_bias0[D];
// pooled per-graph features [g][4*256]
__device__ float g_gbuf[BG * 4 * D];
// K-pair + col-pair packed message weights:
//   g_Wp2[l][kp2*128 + cp] = { (W[k0][2cp],W[k0+1][2cp]), (W[k0][2cp+1],W[k0+1][2cp+1]) }
__device__ ulonglong2 g_Wp2[3][256 * 128];

// ---------------------------------------------------------------------------
// Merged init: blocks 0..16 = folded input-MLP precompute; blocks 17..784 =
// message-weight packing.
// ---------------------------------------------------------------------------
__global__ void init_kernel(const float* __restrict__ Wgeo,
                            const float* __restrict__ bgeo,
                            const float* __restrict__ emb,
                            const float* __restrict__ Wlot,
                            const float* __restrict__ blot,
                            const float* __restrict__ W1,
                            const float* __restrict__ W2,
                            const float* __restrict__ W3)
{
    int b = blockIdx.x;
    if (b < 17) {
        int c = threadIdx.x;
        int r = b;
        float a0 = 0.f, a1 = 0.f, a2 = 0.f, a3 = 0.f;
        if (r < 5) {
            for (int j = 0; j < D; j += 4) {
                a0 = fmaf(Wgeo[r * D + j + 0], Wlot[(j + 0) * D + c], a0);
                a1 = fmaf(Wgeo[r * D + j + 1], Wlot[(j + 1) * D + c], a1);
                a2 = fmaf(Wgeo[r * D + j + 2], Wlot[(j + 2) * D + c], a2);
                a3 = fmaf(Wgeo[r * D + j + 3], Wlot[(j + 3) * D + c], a3);
            }
            g_Mgeo[r * D + c] = (a0 + a1) + (a2 + a3);
        } else if (r < 16) {
            int s = r - 5;
            for (int j = 0; j < D; j += 4) {
                a0 = fmaf(emb[s * D + j + 0], Wlot[(D + j + 0) * D + c], a0);
                a1 = fmaf(emb[s * D + j + 1], Wlot[(D + j + 1) * D + c], a1);
                a2 = fmaf(emb[s * D + j + 2], Wlot[(D + j + 2) * D + c], a2);
                a3 = fmaf(emb[s * D + j + 3], Wlot[(D + j + 3) * D + c], a3);
            }
            g_Msem[s * D + c] = (a0 + a1) + (a2 + a3);
        } else {
            for (int j = 0; j < D; j += 4) {
                a0 = fmaf(bgeo[j + 0], Wlot[(j + 0) * D + c], a0);
                a1 = fmaf(bgeo[j + 1], Wlot[(j + 1) * D + c], a1);
                a2 = fmaf(bgeo[j + 2], Wlot[(j + 2) * D + c], a2);
                a3 = fmaf(bgeo[j + 3], Wlot[(j + 3) * D + c], a3);
            }
            g_bias0[c] = blot[c] + (a0 + a1) + (a2 + a3);
        }
    } else if (threadIdx.x < 128) {
        int bb  = b - 17;
        int l   = bb >> 8;            // 0..2
        int kp2 = bb & 255;           // 0..255
        int cp  = threadIdx.x;        // 0..127
        const float* W = (l == 0) ? W1 : (l == 1) ? W2 : W3;
        int k0 = 2 * kp2;
        int c0 = 2 * cp;
        unsigned lo0 = __float_as_uint(W[k0 * D + c0]);
        unsigned hi0 = __float_as_uint(W[(k0 + 1) * D + c0]);
        unsigned lo1 = __float_as_uint(W[k0 * D + c0 + 1]);
        unsigned hi1 = __float_as_uint(W[(k0 + 1) * D + c0 + 1]);
        ulonglong2 v;
        v.x = (unsigned long long)lo0 | ((unsigned long long)hi0 << 32);
        v.y = (unsigned long long)lo1 | ((unsigned long long)hi1 << 32);
        g_Wp2[l][kp2 * 128 + cp] = v;
    }
}

// ---------------------------------------------------------------------------
// One CTA per graph, 256 threads: tid = rg*128 + cp.
// Thread (rg, cp) owns cols {2cp, 2cp+1} for rows [16rg, 16rg+16).
// 256 threads + <=128 regs => 2 CTAs resident per SM: one CTA's gather/sync
// bubbles overlap the other's FMA2 stream (the 512-thread version ran 1
// CTA/SM and sat at ~2x the FFMA2 pipe floor).
// ---------------------------------------------------------------------------
__global__ void __launch_bounds__(256, 2)
graph_kernel(const float* __restrict__ geometry,
             const int*   __restrict__ semantic,
             const int*   __restrict__ e_src,
             const int*   __restrict__ e_dst,
             const float* __restrict__ Wlot,
             const float* __restrict__ bmp1,
             const float* __restrict__ bmp2,
             const float* __restrict__ bmp3)
{
    extern __shared__ float smem[];
    float* sh_h  = smem;                  // NP*D = 8192
    float* sh_xa = sh_h + NP * D;         // NP*D = 8192
    float* smax  = sh_xa + NP * D;        // 2*D
    float* s_geo = smax + 2 * D;          // NB*5
    float* s_inv = s_geo + NB * 5;        // NB
    int*   s_sem = (int*)(s_inv + NB);    // NB
    int*   s_cnt = s_sem + NB;            // NB
    int*   s_off = s_cnt + NB;            // NB+1
    int*   s_cur = s_off + NB + 1;        // NB
    int*   s_list = s_cur + NB;           // EG

    const int g   = blockIdx.x;
    const int tid = threadIdx.x;
    const int cp  = tid & 127;
    const int rg  = tid >> 7;             // 0..1
    const int c0  = 2 * cp;
    const int r0  = rg * RT;

    // ---- per-graph data, degrees, CSR ----
    for (int i = tid; i < NB * 5; i += 256) s_geo[i] = geometry[g * NB * 5 + i];
    if (tid < NB) { s_sem[tid] = semantic[g * NB + tid]; s_cnt[tid] = 0; }
    __syncthreads();
    if (tid < EG) {
        int d = e_dst[g * EG + tid] - g * NB;
        atomicAdd(&s_cnt[d], 1);
    }
    __syncthreads();
    if (tid == 0) {
        int a = 0;
        for (int i = 0; i < NB; i++) { s_off[i] = a; s_cur[i] = a; a += s_cnt[i]; }
        s_off[NB] = a;
    }
    if (tid < NB) s_inv[tid] = s_cnt[tid] ? 1.0f / (float)s_cnt[tid] : 0.0f;
    __syncthreads();
    if (tid < EG) {
        int s = e_src[g * EG + tid] - g * NB;
        int d = e_dst[g * EG + tid] - g * NB;
        int p = atomicAdd(&s_cur[d], 1);
        s_list[p] = s;
    }

    // ---- h0 ----
    {
        float2 mg[5];
        #pragma unroll
        for (int j = 0; j < 5; j++) mg[j] = *(const float2*)(g_Mgeo + j * D + c0);
        const float2 b0 = *(const float2*)(g_bias0 + c0);
        float2 pm = make_float2(0.f, 0.f);
        #pragma unroll
        for (int i = 0; i < RT; i++) {
            int n = r0 + i;
            float2 v = make_float2(0.f, 0.f);
            if (n < NB) {
                float2 wl = *(const float2*)(Wlot + (2 * D + n) * D + c0);
                float2 ms = *(const float2*)(g_Msem + s_sem[n] * D + c0);
                v = make_float2(b0.x + wl.x + ms.x, b0.y + wl.y + ms.y);
                #pragma unroll
                for (int j = 0; j < 5; j++) {
                    float ge = s_geo[n * 5 + j];
                    v.x = fmaf(ge, mg[j].x, v.x);
                    v.y = fmaf(ge, mg[j].y, v.y);
                }
                v.x = fmaxf(v.x, 0.f); v.y = fmaxf(v.y, 0.f);
            }
            *(float2*)(sh_h + n * D + c0) = v;
            pm.x = fmaxf(pm.x, v.x); pm.y = fmaxf(pm.y, v.y);
        }
        *(float2*)(smax + rg * D + c0) = pm;
    }
    __syncthreads();
    g_gbuf[g * 1024 + 0 * D + tid] = fmaxf(smax[tid], smax[D + tid]);

    // ---- 3 message-passing layers ----
    const float* bms[3] = { bmp1, bmp2, bmp3 };

    for (int l = 0; l < 3; l++) {
        // gather: xa[n] = mean_{src in N(n)} h[src]
        #pragma unroll
        for (int i = 0; i < RT; i++) {
            int n = r0 + i;
            float2 a = make_float2(0.f, 0.f);
            if (n < NB) {
                int e1 = s_off[n + 1];
                for (int e = s_off[n]; e < e1; e++) {
                    float2 hv = *(const float2*)(sh_h + s_list[e] * D + c0);
                    a.x += hv.x; a.y += hv.y;
                }
                float inv = s_inv[n];
                a.x *= inv; a.y *= inv;
            }
            *(float2*)(sh_xa + n * D + c0) = a;
        }
        __syncthreads();

        // GEMM (f32x2, K-pair packed): 16 rows x 2 cols per thread
        const float2 bm = *(const float2*)(bms[l] + c0);
        unsigned long long acc[RT][2];
        #pragma unroll
        for (int i = 0; i < RT; i++) {
            acc[i][0] = (unsigned long long)__float_as_uint(bm.x);
            acc[i][1] = (unsigned long long)__float_as_uint(bm.y);
        }

        #pragma unroll
        for (int part = 0; part < 2; part++) {
            const float* A = part ? sh_xa : sh_h;
            const ulonglong2* Wb = g_Wp2[l] + part * 128 * 128 + cp;
            #pragma unroll 2
            for (int kpl = 0; kpl < 128; kpl += 2) {
                ulonglong2 w0 = Wb[(kpl + 0) * 128];
                ulonglong2 w1 = Wb[(kpl + 1) * 128];
                const float* Ak = A + r0 * D + 2 * kpl;
                #pragma unroll
                for (int i = 0; i < RT; i++) {
                    ulonglong2 hv = *reinterpret_cast<const ulonglong2*>(Ak + i * D);
                    FMA2(acc[i][0], hv.x, w0.x);
                    FMA2(acc[i][1], hv.x, w0.y);
                    FMA2(acc[i][0], hv.y, w1.x);
                    FMA2(acc[i][1], hv.y, w1.y);
                }
            }
        }
        __syncthreads();   // all reads of sh_h / sh_xa done

        float2 pm = make_float2(0.f, 0.f);
        #pragma unroll
        for (int i = 0; i < RT; i++) {
            int n = r0 + i;
            float2 v = make_float2(0.f, 0.f);
            if (n < NB && s_cnt[n]) {      // cnt=0 / padded -> exact 0
                float x = __uint_as_float((unsigned)acc[i][0])
                        + __uint_as_float((unsigned)(acc[i][0] >> 32));
                float y = __uint_as_float((unsigned)acc[i][1])
                        + __uint_as_float((unsigned)(acc[i][1] >> 32));
                v.x = fmaxf(x, 0.f);
                v.y = fmaxf(y, 0.f);
            }
            *(float2*)(sh_h + n * D + c0) = v;
            pm.x = fmaxf(pm.x, v.x); pm.y = fmaxf(pm.y, v.y);
        }
        *(float2*)(smax + rg * D + c0) = pm;
        __syncthreads();
        g_gbuf[g * 1024 + (l + 1) * D + tid] = fmaxf(smax[tid], smax[D + tid]);
    }
}

// ---------------------------------------------------------------------------
// Readout: latent = g @ Wagg + b; mu/logvar = latent @ Wmu/Wvar + b.
// Pooled vectors staged to smem once; W streams coalesced from L2.
// ---------------------------------------------------------------------------
__global__ void __launch_bounds__(256)
aux_kernel(const float* __restrict__ Wagg, const float* __restrict__ bagg,
           const float* __restrict__ Wmu,  const float* __restrict__ bmu,
           const float* __restrict__ Wvar, const float* __restrict__ bvar,
           float* __restrict__ out)
{
    __shared__ float sh_g[GAUX * 1024];    // 32 KB
    __shared__ float sh_lat[GAUX * D];     // 8 KB
    const int c  = threadIdx.x;
    const int g0 = blockIdx.x * GAUX;

    {
        const float4* src = (const float4*)(g_gbuf + g0 * 1024);
        float4* dst = (float4*)sh_g;
        #pragma unroll
        for (int i = 0; i < GAUX * 1024 / 4 / 256; i++)
            dst[i * 256 + c] = src[i * 256 + c];
    }
    __syncthreads();

    float lat[GAUX];
    {
        float bg = bagg[c];
        #pragma unroll
        for (int i = 0; i < GAUX; i++) lat[i] = bg;
    }
    for (int k4 = 0; k4 < 4 * D; k4 += 4) {
        float w0 = Wagg[(k4 + 0) * D + c];
        float w1 = Wagg[(k4 + 1) * D + c];
        float w2 = Wagg[(k4 + 2) * D + c];
        float w3 = Wagg[(k4 + 3) * D + c];
        #pragma unroll
        for (int i = 0; i < GAUX; i++) {
            float4 gv = *(const float4*)(sh_g + i * 1024 + k4);
            lat[i] = fmaf(gv.x, w0, fmaf(gv.y, w1, fmaf(gv.z, w2, fmaf(gv.w, w3, lat[i]))));
        }
    }
    __syncthreads();
    #pragma unroll
    for (int i = 0; i < GAUX; i++) sh_lat[i * D + c] = lat[i];
    __syncthreads();

    float mu[GAUX], lv[GAUX];
    {
        float bm_ = bmu[c], bv_ = bvar[c];
        #pragma unroll
        for (int i = 0; i < GAUX; i++) { mu[i] = bm_; lv[i] = bv_; }
    }
    for (int j4 = 0; j4 < D; j4 += 4) {
        float m0 = Wmu[(j4 + 0) * D + c],  m1 = Wmu[(j4 + 1) * D + c];
        float m2 = Wmu[(j4 + 2) * D + c],  m3 = Wmu[(j4 + 3) * D + c];
        float v0 = Wvar[(j4 + 0) * D + c], v1 = Wvar[(j4 + 1) * D + c];
        float v2 = Wvar[(j4 + 2) * D + c], v3 = Wvar[(j4 + 3) * D + c];
        #pragma unroll
        for (int i = 0; i < GAUX; i++) {
            float4 L = *(const float4*)(sh_lat + i * D + j4);
            mu[i] = fmaf(L.x, m0, fmaf(L.y, m1, fmaf(L.z, m2, fmaf(L.w, m3, mu[i]))));
            lv[i] = fmaf(L.x, v0, fmaf(L.y, v1, fmaf(L.z, v2, fmaf(L.w, v3, lv[i]))));
        }
    }
    #pragma unroll
    for (int i = 0; i < GAUX; i++) {
        out[(g0 + i) * D + c]          = mu[i];
        out[BG * D + (g0 + i) * D + c] = lv[i];
    }
}

// ---------------------------------------------------------------------------
extern "C" void kernel_launch(void* const* d_in, const int* in_sizes, int n_in,
                              void* d_out, int out_size)
{
    const float* geometry = (const float*)d_in[0];
    const int*   semantic = (const int*)d_in[1];
    const int*   eidx     = (const int*)d_in[2];
    const float* Wgeo = (const float*)d_in[4];
    const float* bgeo = (const float*)d_in[5];
    const float* emb  = (const float*)d_in[6];
    const float* Wlot = (const float*)d_in[7];
    const float* blot = (const float*)d_in[8];
    const float* Wmp1 = (const float*)d_in[9];
    const float* bmp1 = (const float*)d_in[10];
    const float* Wmp2 = (const float*)d_in[11];
    const float* bmp2 = (const float*)d_in[12];
    const float* Wmp3 = (const float*)d_in[13];
    const float* bmp3 = (const float*)d_in[14];
    const float* Wagg = (const float*)d_in[15];
    const float* bagg = (const float*)d_in[16];
    const float* Wmu  = (const float*)d_in[17];
    const float* bmu  = (const float*)d_in[18];
    const float* Wvar = (const float*)d_in[19];
    const float* bvar = (const float*)d_in[20];

    const int n_edges = in_sizes[2] / 2;
    const int* e_src = eidx;
    const int* e_dst = eidx + n_edges;

    init_kernel<<<17 + 3 * 256, 256>>>(Wgeo, bgeo, emb, Wlot, blot,
                                       Wmp1, Wmp2, Wmp3);

    size_t smem_bytes = (2 * NP * D + 2 * D + NB * 5 + NB) * sizeof(float)
                      + (3 * NB + 1 + EG) * sizeof(int) + 64;
    cudaFuncSetAttribute(graph_kernel, cudaFuncAttributeMaxDynamicSharedMemorySize,
                         (int)smem_bytes);

    graph_kernel<<<BG, 256, smem_bytes>>>(
        geometry, semantic, e_src, e_dst, Wlot, bmp1, bmp2, bmp3);

    aux_kernel<<<BG / GAUX, 256>>>(Wagg, bagg, Wmu, bmu, Wvar, bvar, (float*)d_out);
}